// round 6
// baseline (speedup 1.0000x reference)
#include <cuda_runtime.h>
#include <cuda_bf16.h>
#include <math.h>
#include <stdint.h>

// Problem constants
#define T_DIM 2048
#define B_DIM 8
#define F_DIM 768
#define H_DIM 3
#define DH    256
#define M_ROWS (T_DIM * B_DIM)   // 16384
#define ROW_STRIDE 6144          // B_DIM * F_DIM
#define XN (M_ROWS * F_DIM)      // 12582912
#define WN (F_DIM * F_DIM)       // 589824

// Scratch (allocation-free: device globals)
__device__ float g_Q[XN];
__device__ float g_K[XN];
__device__ float g_V[XN];
__device__ float g_O[XN];
__device__ __nv_bfloat16 g_xh[XN], g_xl[XN];
__device__ __nv_bfloat16 g_Oh[XN], g_Ol[XN];
__device__ __nv_bfloat16 g_Wh[4][WN], g_Wl[4][WN];

// ---------------------------------------------------------------------------
// helpers
// ---------------------------------------------------------------------------
__device__ __forceinline__ float to_tf32(float x) {
    uint32_t u;
    asm("cvt.rna.tf32.f32 %0, %1;" : "=r"(u) : "f"(x));
    return __uint_as_float(u);
}

__device__ __forceinline__ void mma8(float c[4],
                                     uint32_t a0, uint32_t a1, uint32_t a2, uint32_t a3,
                                     uint32_t b0, uint32_t b1) {
    asm volatile(
        "mma.sync.aligned.m16n8k8.row.col.f32.tf32.tf32.f32 "
        "{%0,%1,%2,%3}, {%4,%5,%6,%7}, {%8,%9}, {%0,%1,%2,%3};"
        : "+f"(c[0]), "+f"(c[1]), "+f"(c[2]), "+f"(c[3])
        : "r"(a0), "r"(a1), "r"(a2), "r"(a3), "r"(b0), "r"(b1));
}

__device__ __forceinline__ void mma16(float c[4], const uint32_t a[4],
                                      uint32_t b0, uint32_t b1) {
    asm volatile(
        "mma.sync.aligned.m16n8k16.row.col.f32.bf16.bf16.f32 "
        "{%0,%1,%2,%3}, {%4,%5,%6,%7}, {%8,%9}, {%0,%1,%2,%3};"
        : "+f"(c[0]), "+f"(c[1]), "+f"(c[2]), "+f"(c[3])
        : "r"(a[0]), "r"(a[1]), "r"(a[2]), "r"(a[3]), "r"(b0), "r"(b1));
}

#define LDSM_X4(R, addr)                                                    \
    asm volatile("ldmatrix.sync.aligned.m8n8.x4.shared.b16 "                \
                 "{%0,%1,%2,%3}, [%4];"                                     \
                 : "=r"((R)[0]), "=r"((R)[1]), "=r"((R)[2]), "=r"((R)[3])   \
                 : "r"(addr))

#define CP_ASYNC16(dst, src)                                                \
    asm volatile("cp.async.cg.shared.global [%0], [%1], 16;"                \
                 :: "r"(dst), "l"(src))
#define CP_COMMIT()  asm volatile("cp.async.commit_group;" ::: "memory")
#define CP_WAIT0()   asm volatile("cp.async.wait_group 0;" ::: "memory")

// split fp32x4 into bf16 hi/lo and store (4 contiguous elems)
__device__ __forceinline__ void split4(__nv_bfloat16* hp, __nv_bfloat16* lp, float4 v) {
    __nv_bfloat16 h0 = __float2bfloat16(v.x);
    __nv_bfloat16 h1 = __float2bfloat16(v.y);
    __nv_bfloat16 h2 = __float2bfloat16(v.z);
    __nv_bfloat16 h3 = __float2bfloat16(v.w);
    __nv_bfloat162 hh0; hh0.x = h0; hh0.y = h1;
    __nv_bfloat162 hh1; hh1.x = h2; hh1.y = h3;
    *(__nv_bfloat162*)hp       = hh0;
    *((__nv_bfloat162*)hp + 1) = hh1;
    __nv_bfloat162 ll0, ll1;
    ll0.x = __float2bfloat16(v.x - __bfloat162float(h0));
    ll0.y = __float2bfloat16(v.y - __bfloat162float(h1));
    ll1.x = __float2bfloat16(v.z - __bfloat162float(h2));
    ll1.y = __float2bfloat16(v.w - __bfloat162float(h3));
    *(__nv_bfloat162*)lp       = ll0;
    *((__nv_bfloat162*)lp + 1) = ll1;
}

// elementwise split kernel: fp32 -> bf16 hi/lo
__global__ __launch_bounds__(256) void split_kernel(
    const float* __restrict__ in, __nv_bfloat16* __restrict__ hi,
    __nv_bfloat16* __restrict__ lo, int n)
{
    int i = (blockIdx.x * 256 + threadIdx.x) * 4;
    if (i < n) {
        float4 v = *(const float4*)&in[i];
        split4(&hi[i], &lo[i], v);
    }
}

// ---------------------------------------------------------------------------
// Pre-split bf16 tensor-core GEMM: C = A*W^T + bias, 3-term bf16 (AhWh+AhWl+AlWh)
// BM=128, BN=128, BK=32, 256 threads (8 warps 4x2), warp tile 32x64.
// cp.async double-buffered; smem bf16 stride 40 (80B) -> ldmatrix conflict-free.
// ---------------------------------------------------------------------------
#define GQ_STR  40
#define GQ_TILE (128 * GQ_STR)               // bf16 elems per operand tile
#define GEMM_SMEM_BYTES (2 * 4 * GQ_TILE * 2) // 81920

__global__ __launch_bounds__(256, 2) void gemm_bf16p_kernel(
    const __nv_bfloat16* __restrict__ Ah, const __nv_bfloat16* __restrict__ Al,
    const __nv_bfloat16* __restrict__ Bh, const __nv_bfloat16* __restrict__ Bl,
    const float* __restrict__ bias, float* __restrict__ C,
    int M, int N, int K, int round_out)
{
    extern __shared__ __nv_bfloat16 gsm[];   // [2][4][GQ_TILE]
    const uint32_t sbase = (uint32_t)__cvta_generic_to_shared(gsm);

    const int tid  = threadIdx.x;
    const int lane = tid & 31;
    const int w    = tid >> 5;
    const int g    = lane >> 2;
    const int tg   = lane & 3;
    const int wr   = w >> 1;       // 0..3 (m)
    const int wc   = w & 1;        // 0..1 (n)

    const int m0 = blockIdx.y * 128;
    const int n0 = blockIdx.x * 128;

    const int arow = wr * 32;
    const int brow = wc * 64;

    // loader mapping: per operand tile, 512 16B-chunks; 2 per thread
    const int lrow0 = tid >> 2;          // 0..63
    const int lrow1 = lrow0 + 64;        // 64..127
    const int lc    = tid & 3;           // chunk (8 bf16 each)

    // fragment byte offsets within a tile
    const int lr16 = lane & 15;
    const uint32_t a_base = (uint32_t)((arow + lr16) * GQ_STR * 2 + (lane >> 4) * 16);
    const uint32_t b_base = (uint32_t)((brow + ((lane >> 4) << 3) + (lane & 7)) * GQ_STR * 2
                                       + (((lane >> 3) & 1) << 4));

    float acc[2][8][4];
#pragma unroll
    for (int mi = 0; mi < 2; mi++)
#pragma unroll
        for (int nt = 0; nt < 8; nt++)
#pragma unroll
            for (int j = 0; j < 4; j++) acc[mi][nt][j] = 0.f;

    // stage loader
    auto loadStage = [&](int stg, int k0) {
        const uint32_t s0 = sbase + (uint32_t)(stg * 4 * GQ_TILE * 2);
        const uint32_t d0 = (uint32_t)(lrow0 * GQ_STR * 2 + lc * 16);
        const uint32_t d1 = (uint32_t)(lrow1 * GQ_STR * 2 + lc * 16);
        const size_t ga0 = (size_t)(m0 + lrow0) * K + k0 + lc * 8;
        const size_t ga1 = (size_t)(m0 + lrow1) * K + k0 + lc * 8;
        const size_t gb0 = (size_t)(n0 + lrow0) * K + k0 + lc * 8;
        const size_t gb1 = (size_t)(n0 + lrow1) * K + k0 + lc * 8;
        CP_ASYNC16(s0 + 0 * (GQ_TILE * 2) + d0, Ah + ga0);
        CP_ASYNC16(s0 + 0 * (GQ_TILE * 2) + d1, Ah + ga1);
        CP_ASYNC16(s0 + 1 * (GQ_TILE * 2) + d0, Al + ga0);
        CP_ASYNC16(s0 + 1 * (GQ_TILE * 2) + d1, Al + ga1);
        CP_ASYNC16(s0 + 2 * (GQ_TILE * 2) + d0, Bh + gb0);
        CP_ASYNC16(s0 + 2 * (GQ_TILE * 2) + d1, Bh + gb1);
        CP_ASYNC16(s0 + 3 * (GQ_TILE * 2) + d0, Bl + gb0);
        CP_ASYNC16(s0 + 3 * (GQ_TILE * 2) + d1, Bl + gb1);
    };

    loadStage(0, 0);
    CP_COMMIT();

    const int nIter = K / 32;   // 24
    for (int it = 0; it < nIter; ++it) {
        const int cur = it & 1;
        CP_WAIT0();
        __syncthreads();
        if (it + 1 < nIter) {
            loadStage(cur ^ 1, (it + 1) * 32);
            CP_COMMIT();
        }

        const uint32_t sAh = sbase + (uint32_t)((cur * 4 + 0) * GQ_TILE * 2);
        const uint32_t sAl = sbase + (uint32_t)((cur * 4 + 1) * GQ_TILE * 2);
        const uint32_t sBh = sbase + (uint32_t)((cur * 4 + 2) * GQ_TILE * 2);
        const uint32_t sBl = sbase + (uint32_t)((cur * 4 + 3) * GQ_TILE * 2);

        uint32_t ah[2][2][4], al[2][2][4];
#pragma unroll
        for (int mi = 0; mi < 2; mi++)
#pragma unroll
            for (int kk = 0; kk < 2; kk++) {
                const uint32_t off = a_base + mi * (16 * GQ_STR * 2) + kk * 32;
                LDSM_X4(ah[mi][kk], sAh + off);
                LDSM_X4(al[mi][kk], sAl + off);
            }

#pragma unroll
        for (int p = 0; p < 4; p++) {
            uint32_t bh[2][4], bl[2][4];
#pragma unroll
            for (int kk = 0; kk < 2; kk++) {
                const uint32_t off = b_base + p * (16 * GQ_STR * 2) + kk * 32;
                LDSM_X4(bh[kk], sBh + off);
                LDSM_X4(bl[kk], sBl + off);
            }
#pragma unroll
            for (int j = 0; j < 2; j++) {
                const int nt = p * 2 + j;
#pragma unroll
                for (int mi = 0; mi < 2; mi++) {
#pragma unroll
                    for (int kk = 0; kk < 2; kk++) {
                        mma16(acc[mi][nt], ah[mi][kk], bh[kk][2 * j], bh[kk][2 * j + 1]);
                        mma16(acc[mi][nt], ah[mi][kk], bl[kk][2 * j], bl[kk][2 * j + 1]);
                        mma16(acc[mi][nt], al[mi][kk], bh[kk][2 * j], bh[kk][2 * j + 1]);
                    }
                }
            }
        }
        __syncthreads();
    }

    // epilogue: bias + (optional tf32 round) + store
#pragma unroll
    for (int nt = 0; nt < 8; nt++) {
        int c0 = n0 + brow + nt * 8 + tg * 2;
        float2 bb = *(const float2*)&bias[c0];
#pragma unroll
        for (int mi = 0; mi < 2; mi++) {
            int r0 = m0 + arow + mi * 16 + g;
            float2 o0 = make_float2(acc[mi][nt][0] + bb.x, acc[mi][nt][1] + bb.y);
            float2 o1 = make_float2(acc[mi][nt][2] + bb.x, acc[mi][nt][3] + bb.y);
            if (round_out) {
                o0.x = to_tf32(o0.x); o0.y = to_tf32(o0.y);
                o1.x = to_tf32(o1.x); o1.y = to_tf32(o1.y);
            }
            *(float2*)&C[(size_t)r0 * N + c0]       = o0;
            *(float2*)&C[(size_t)(r0 + 8) * N + c0] = o1;
        }
    }
}

// ---------------------------------------------------------------------------
// Flash attention v2 (unchanged from R5): tf32 mma + ldmatrix + cp.async.
// ---------------------------------------------------------------------------
#define AQK_STR 260
#define AV_STR  264
#define AP_STR  36
#define KS_OFF  (64 * AQK_STR)
#define VS_OFF  (KS_OFF + 2 * 32 * AQK_STR)
#define PS_OFF  (VS_OFF + 2 * 32 * AV_STR)
#define ST_OFF  (PS_OFF + 64 * AP_STR)
#define ATTN_SMEM_FLOATS (ST_OFF + 192)
#define ATTN_SMEM_BYTES  (ATTN_SMEM_FLOATS * 4)

__global__ __launch_bounds__(256) void attn_tc2_kernel(
    const float* __restrict__ Q, const float* __restrict__ K,
    const float* __restrict__ V, float* __restrict__ O)
{
    extern __shared__ float sm[];
    float* Ps   = sm + PS_OFF;
    float* sm_m = sm + ST_OFF;
    float* sm_l = sm_m + 64;
    float* sm_a = sm_l + 64;

    const uint32_t sbase = (uint32_t)__cvta_generic_to_shared(sm);

    const int tid  = threadIdx.x;
    const int lane = tid & 31;
    const int w    = tid >> 5;
    const int g    = lane >> 2;
    const int tg   = lane & 3;
    const int wr   = w >> 1;
    const int wc   = w & 1;

    const int bh = blockIdx.y;
    const int b  = bh / H_DIM;
    const int h  = bh % H_DIM;
    const int t0 = blockIdx.x * 64;
    const size_t head = (size_t)b * F_DIM + (size_t)h * DH;

    {
        const int r = tid >> 6;
        const int c = tid & 63;
#pragma unroll
        for (int i = 0; i < 4; i++) {
            int row = r + i * 4;
            const float* src = &Q[(size_t)(t0 + row) * ROW_STRIDE + head + c * 4];
            uint32_t dst = sbase + (uint32_t)(row * AQK_STR + c * 4) * 4;
            CP_ASYNC16(dst, src);
            row += 16;
            src = &Q[(size_t)(t0 + row) * ROW_STRIDE + head + c * 4];
            dst = sbase + (uint32_t)(row * AQK_STR + c * 4) * 4;
            CP_ASYNC16(dst, src);
            row += 16;
            src = &Q[(size_t)(t0 + row) * ROW_STRIDE + head + c * 4];
            dst = sbase + (uint32_t)(row * AQK_STR + c * 4) * 4;
            CP_ASYNC16(dst, src);
            row += 16;
            src = &Q[(size_t)(t0 + row) * ROW_STRIDE + head + c * 4];
            dst = sbase + (uint32_t)(row * AQK_STR + c * 4) * 4;
            CP_ASYNC16(dst, src);
        }
        const int kr = tid >> 6, kc = tid & 63;
#pragma unroll
        for (int i = 0; i < 8; i++) {
            int row = kr + i * 4;
            size_t gaddr = (size_t)row * ROW_STRIDE + head + kc * 4;
            CP_ASYNC16(sbase + (uint32_t)(KS_OFF + row * AQK_STR + kc * 4) * 4, &K[gaddr]);
            CP_ASYNC16(sbase + (uint32_t)(VS_OFF + row * AV_STR  + kc * 4) * 4, &V[gaddr]);
        }
        CP_COMMIT();
    }

    if (tid < 64) { sm_m[tid] = -1e30f; sm_l[tid] = 0.f; }

    float oacc[16][4];
#pragma unroll
    for (int nt = 0; nt < 16; nt++)
#pragma unroll
        for (int j = 0; j < 4; j++) oacc[nt][j] = 0.f;

    const int rq = wr * 16, ck = wc * 16;
    const int ro = wr * 16, co = wc * 128;

    const int lr16 = lane & 15;
    const int lcA  = (lane >> 4) * 4;
    const uint32_t qoff = sbase + (uint32_t)((rq + lr16) * AQK_STR + lcA) * 4;
    const uint32_t koff_l = (uint32_t)((ck + ((lane >> 4) << 3) + (lane & 7)) * AQK_STR
                                       + ((lane >> 3) & 1) * 4) * 4;
    const uint32_t poff = sbase + (uint32_t)(PS_OFF + (ro + lr16) * AP_STR + lcA) * 4;

    const int sr = tid >> 2, qd = tid & 3;

    for (int t = 0; t < 64; ++t) {
        const int cur = t & 1;
        CP_WAIT0();
        __syncthreads();

        if (t + 1 < 64) {
            const int nxt = cur ^ 1;
            const int s0 = (t + 1) * 32;
            const int kr = tid >> 6, kc = tid & 63;
#pragma unroll
            for (int i = 0; i < 8; i++) {
                int row = kr + i * 4;
                size_t gaddr = (size_t)(s0 + row) * ROW_STRIDE + head + kc * 4;
                CP_ASYNC16(sbase + (uint32_t)(KS_OFF + (nxt * 32 + row) * AQK_STR + kc * 4) * 4, &K[gaddr]);
                CP_ASYNC16(sbase + (uint32_t)(VS_OFF + (nxt * 32 + row) * AV_STR  + kc * 4) * 4, &V[gaddr]);
            }
            CP_COMMIT();
        }

        float sacc[2][4];
#pragma unroll
        for (int nt = 0; nt < 2; nt++)
#pragma unroll
            for (int j = 0; j < 4; j++) sacc[nt][j] = 0.f;

        const uint32_t kbase = sbase + (uint32_t)(KS_OFF + cur * 32 * AQK_STR) * 4 + koff_l;
#pragma unroll
        for (int k0 = 0; k0 < DH; k0 += 8) {
            uint32_t a[4], bb[4];
            LDSM_X4(a,  qoff  + k0 * 4);
            LDSM_X4(bb, kbase + k0 * 4);
            mma8(sacc[0], a[0], a[1], a[2], a[3], bb[0], bb[1]);
            mma8(sacc[1], a[0], a[1], a[2], a[3], bb[2], bb[3]);
        }

#pragma unroll
        for (int nt = 0; nt < 2; nt++) {
            int c0 = ck + nt * 8 + tg * 2;
            *(float2*)&Ps[(rq + g)     * AP_STR + c0] = make_float2(sacc[nt][0], sacc[nt][1]);
            *(float2*)&Ps[(rq + g + 8) * AP_STR + c0] = make_float2(sacc[nt][2], sacc[nt][3]);
        }
        __syncthreads();

        {
            float* row = &Ps[sr * AP_STR + qd * 8];
            float4 v0 = *(float4*)&row[0];
            float4 v1 = *(float4*)&row[4];
            const float sc = 0.125f;
            v0.x *= sc; v0.y *= sc; v0.z *= sc; v0.w *= sc;
            v1.x *= sc; v1.y *= sc; v1.z *= sc; v1.w *= sc;

            float mx = fmaxf(fmaxf(fmaxf(v0.x, v0.y), fmaxf(v0.z, v0.w)),
                             fmaxf(fmaxf(v1.x, v1.y), fmaxf(v1.z, v1.w)));
            mx = fmaxf(mx, __shfl_xor_sync(0xffffffffu, mx, 1));
            mx = fmaxf(mx, __shfl_xor_sync(0xffffffffu, mx, 2));

            float m_old = sm_m[sr];
            float m_new = fmaxf(m_old, mx);
            float alpha = __expf(m_old - m_new);

            v0.x = __expf(v0.x - m_new); v0.y = __expf(v0.y - m_new);
            v0.z = __expf(v0.z - m_new); v0.w = __expf(v0.w - m_new);
            v1.x = __expf(v1.x - m_new); v1.y = __expf(v1.y - m_new);
            v1.z = __expf(v1.z - m_new); v1.w = __expf(v1.w - m_new);

            float s = (v0.x + v0.y + v0.z + v0.w) + (v1.x + v1.y + v1.z + v1.w);
            s += __shfl_xor_sync(0xffffffffu, s, 1);
            s += __shfl_xor_sync(0xffffffffu, s, 2);

            v0.x = to_tf32(v0.x); v0.y = to_tf32(v0.y);
            v0.z = to_tf32(v0.z); v0.w = to_tf32(v0.w);
            v1.x = to_tf32(v1.x); v1.y = to_tf32(v1.y);
            v1.z = to_tf32(v1.z); v1.w = to_tf32(v1.w);
            *(float4*)&row[0] = v0;
            *(float4*)&row[4] = v1;

            if (qd == 0) {
                sm_m[sr] = m_new;
                sm_l[sr] = sm_l[sr] * alpha + s;
                sm_a[sr] = alpha;
            }
        }
        __syncthreads();

        {
            float al0 = sm_a[ro + g];
            float al1 = sm_a[ro + g + 8];
#pragma unroll
            for (int nt = 0; nt < 16; nt++) {
                oacc[nt][0] *= al0; oacc[nt][1] *= al0;
                oacc[nt][2] *= al1; oacc[nt][3] *= al1;
            }
        }
        const float* Vsc = sm + VS_OFF + cur * 32 * AV_STR;
#pragma unroll
        for (int k0 = 0; k0 < 32; k0 += 8) {
            uint32_t a[4];
            LDSM_X4(a, poff + k0 * 4);
            const float* vr0 = &Vsc[(k0 + tg)     * AV_STR + co + g];
            const float* vr1 = &Vsc[(k0 + tg + 4) * AV_STR + co + g];
#pragma unroll
            for (int nt = 0; nt < 16; nt++) {
                uint32_t b0 = __float_as_uint(vr0[nt * 8]);
                uint32_t b1 = __float_as_uint(vr1[nt * 8]);
                mma8(oacc[nt], a[0], a[1], a[2], a[3], b0, b1);
            }
        }
    }

    {
        float il0 = 1.f / sm_l[ro + g];
        float il1 = 1.f / sm_l[ro + g + 8];
        size_t r0 = (size_t)(t0 + ro + g)     * ROW_STRIDE + head + co;
        size_t r1 = (size_t)(t0 + ro + g + 8) * ROW_STRIDE + head + co;
#pragma unroll
        for (int nt = 0; nt < 16; nt++) {
            int c0 = nt * 8 + tg * 2;
            *(float2*)&O[r0 + c0] = make_float2(oacc[nt][0] * il0, oacc[nt][1] * il0);
            *(float2*)&O[r1 + c0] = make_float2(oacc[nt][2] * il1, oacc[nt][3] * il1);
        }
    }
}

// ---------------------------------------------------------------------------
extern "C" void kernel_launch(void* const* d_in, const int* in_sizes, int n_in,
                              void* d_out, int out_size)
{
    const float* x  = (const float*)d_in[0];
    const float* Wq = (const float*)d_in[1];
    const float* bq = (const float*)d_in[2];
    const float* Wk = (const float*)d_in[3];
    const float* bk = (const float*)d_in[4];
    const float* Wv = (const float*)d_in[5];
    const float* bv = (const float*)d_in[6];
    const float* Wo = (const float*)d_in[7];
    const float* bo = (const float*)d_in[8];
    float* out = (float*)d_out;

    float *Qp, *Kp, *Vp, *Op;
    cudaGetSymbolAddress((void**)&Qp, g_Q);
    cudaGetSymbolAddress((void**)&Kp, g_K);
    cudaGetSymbolAddress((void**)&Vp, g_V);
    cudaGetSymbolAddress((void**)&Op, g_O);

    __nv_bfloat16 *xh, *xl, *Oh, *Ol, *Wh, *Wl;
    cudaGetSymbolAddress((void**)&xh, g_xh);
    cudaGetSymbolAddress((void**)&xl, g_xl);
    cudaGetSymbolAddress((void**)&Oh, g_Oh);
    cudaGetSymbolAddress((void**)&Ol, g_Ol);
    cudaGetSymbolAddress((void**)&Wh, g_Wh);
    cudaGetSymbolAddress((void**)&Wl, g_Wl);

    // pre-split x and all weights
    split_kernel<<<XN / (256 * 4), 256>>>(x, xh, xl, XN);
    split_kernel<<<WN / (256 * 4), 256>>>(Wq, Wh + 0 * WN, Wl + 0 * WN, WN);
    split_kernel<<<WN / (256 * 4), 256>>>(Wk, Wh + 1 * WN, Wl + 1 * WN, WN);
    split_kernel<<<WN / (256 * 4), 256>>>(Wv, Wh + 2 * WN, Wl + 2 * WN, WN);
    split_kernel<<<WN / (256 * 4), 256>>>(Wo, Wh + 3 * WN, Wl + 3 * WN, WN);

    cudaFuncSetAttribute(gemm_bf16p_kernel,
                         cudaFuncAttributeMaxDynamicSharedMemorySize,
                         GEMM_SMEM_BYTES);
    dim3 ggrid(F_DIM / 128, M_ROWS / 128);   // (6, 128)

    gemm_bf16p_kernel<<<ggrid, 256, GEMM_SMEM_BYTES>>>(
        xh, xl, Wh + 0 * WN, Wl + 0 * WN, bq, Qp, M_ROWS, F_DIM, F_DIM, 1);
    gemm_bf16p_kernel<<<ggrid, 256, GEMM_SMEM_BYTES>>>(
        xh, xl, Wh + 1 * WN, Wl + 1 * WN, bk, Kp, M_ROWS, F_DIM, F_DIM, 1);
    gemm_bf16p_kernel<<<ggrid, 256, GEMM_SMEM_BYTES>>>(
        xh, xl, Wh + 2 * WN, Wl + 2 * WN, bv, Vp, M_ROWS, F_DIM, F_DIM, 1);

    cudaFuncSetAttribute(attn_tc2_kernel,
                         cudaFuncAttributeMaxDynamicSharedMemorySize,
                         ATTN_SMEM_BYTES);
    attn_tc2_kernel<<<dim3(T_DIM / 64, B_DIM * H_DIM), 256, ATTN_SMEM_BYTES>>>(
        Qp, Kp, Vp, Op);

    // split attention output, then final projection
    split_kernel<<<XN / (256 * 4), 256>>>(Op, Oh, Ol, XN);
    gemm_bf16p_kernel<<<ggrid, 256, GEMM_SMEM_BYTES>>>(
        Oh, Ol, Wh + 3 * WN, Wl + 3 * WN, bo, out, M_ROWS, F_DIM, F_DIM, 0);
}

// round 8
// speedup vs baseline: 2.4696x; 2.4696x over previous
#include <cuda_runtime.h>
#include <cuda_fp16.h>
#include <math.h>
#include <stdint.h>

// Problem constants
#define T_DIM 2048
#define B_DIM 8
#define F_DIM 768
#define H_DIM 3
#define DH    256
#define M_ROWS (T_DIM * B_DIM)   // 16384
#define ROW_STRIDE 6144          // B_DIM * F_DIM
#define XN (M_ROWS * F_DIM)      // 12582912
#define WN (F_DIM * F_DIM)       // 589824

// Scratch (allocation-free: device globals)
__device__ __half g_x16[XN];
__device__ __half g_Q16[XN];
__device__ __half g_K16[XN];
__device__ __half g_V16[XN];
__device__ __half g_O16[XN];
__device__ __half g_W16[4][WN];

// ---------------------------------------------------------------------------
// helpers
// ---------------------------------------------------------------------------
#define LDSM_X4(R, addr)                                                    \
    asm volatile("ldmatrix.sync.aligned.m8n8.x4.shared.b16 "                \
                 "{%0,%1,%2,%3}, [%4];"                                     \
                 : "=r"((R)[0]), "=r"((R)[1]), "=r"((R)[2]), "=r"((R)[3])   \
                 : "r"(addr))

#define LDSM_X4T(R, addr)                                                   \
    asm volatile("ldmatrix.sync.aligned.m8n8.x4.trans.shared.b16 "          \
                 "{%0,%1,%2,%3}, [%4];"                                     \
                 : "=r"((R)[0]), "=r"((R)[1]), "=r"((R)[2]), "=r"((R)[3])   \
                 : "r"(addr))

#define MMA16F(c, a, b0, b1)                                                \
    asm volatile(                                                           \
        "mma.sync.aligned.m16n8k16.row.col.f32.f16.f16.f32 "                \
        "{%0,%1,%2,%3}, {%4,%5,%6,%7}, {%8,%9}, {%0,%1,%2,%3};"             \
        : "+f"((c)[0]), "+f"((c)[1]), "+f"((c)[2]), "+f"((c)[3])            \
        : "r"((a)[0]), "r"((a)[1]), "r"((a)[2]), "r"((a)[3]),               \
          "r"(b0), "r"(b1))

#define CP_ASYNC16(dst, src)                                                \
    asm volatile("cp.async.cg.shared.global [%0], [%1], 16;"                \
                 :: "r"(dst), "l"(src))
#define CP_COMMIT()  asm volatile("cp.async.commit_group;" ::: "memory")
#define CP_WAIT0()   asm volatile("cp.async.wait_group 0;" ::: "memory")
#define CP_WAIT1()   asm volatile("cp.async.wait_group 1;" ::: "memory")

// fp32 -> fp16 convert kernels
__global__ __launch_bounds__(256) void conv_half_kernel(
    const float* __restrict__ in, __half* __restrict__ out, int n)
{
    int i = (blockIdx.x * 256 + threadIdx.x) * 8;
    if (i < n) {
        float4 a = *(const float4*)&in[i];
        float4 b = *(const float4*)&in[i + 4];
        __half2 h0 = __floats2half2_rn(a.x, a.y);
        __half2 h1 = __floats2half2_rn(a.z, a.w);
        __half2 h2 = __floats2half2_rn(b.x, b.y);
        __half2 h3 = __floats2half2_rn(b.z, b.w);
        uint4 u;
        u.x = *(uint32_t*)&h0; u.y = *(uint32_t*)&h1;
        u.z = *(uint32_t*)&h2; u.w = *(uint32_t*)&h3;
        *(uint4*)&out[i] = u;
    }
}

__global__ __launch_bounds__(256) void conv_w4_kernel(
    const float* __restrict__ w0, const float* __restrict__ w1,
    const float* __restrict__ w2, const float* __restrict__ w3,
    __half* __restrict__ out)
{
    const float* src = blockIdx.y == 0 ? w0 : blockIdx.y == 1 ? w1
                      : blockIdx.y == 2 ? w2 : w3;
    __half* dst = out + (size_t)blockIdx.y * WN;
    int i = (blockIdx.x * 256 + threadIdx.x) * 8;
    if (i < WN) {
        float4 a = *(const float4*)&src[i];
        float4 b = *(const float4*)&src[i + 4];
        __half2 h0 = __floats2half2_rn(a.x, a.y);
        __half2 h1 = __floats2half2_rn(a.z, a.w);
        __half2 h2 = __floats2half2_rn(b.x, b.y);
        __half2 h3 = __floats2half2_rn(b.z, b.w);
        uint4 u;
        u.x = *(uint32_t*)&h0; u.y = *(uint32_t*)&h1;
        u.z = *(uint32_t*)&h2; u.w = *(uint32_t*)&h3;
        *(uint4*)&dst[i] = u;
    }
}

// ---------------------------------------------------------------------------
// fp16 tensor-core GEMM: C[m,n] = sum_k A[m,k]*W[n,k] + bias[n].
// BM=128, BN=128, BK=64, 256 threads (8 warps 4x2), warp tile 32x64.
// 3-stage cp.async pipeline; smem fp16 stride 72 (144B) -> ldsm conflict-free.
// grid.z selects {Wq,Wk,Wv} slice + bias + fp16 output; of!=null -> f32 out.
// ---------------------------------------------------------------------------
#define G_STR 72
#define G_TILE_B (128 * G_STR * 2)   // 18432
#define G_STAGE_B (2 * G_TILE_B)     // A + B
#define GEMM_SMEM_BYTES (3 * G_STAGE_B)  // 110592

__global__ __launch_bounds__(256, 2) void gemm_fp16_kernel(
    const __half* __restrict__ A, const __half* __restrict__ W0,
    const float* __restrict__ b0, const float* __restrict__ b1,
    const float* __restrict__ b2,
    __half* __restrict__ o0, __half* __restrict__ o1, __half* __restrict__ o2,
    float* __restrict__ of, int M, int N, int K)
{
    extern __shared__ char gsm[];
    const uint32_t sbase = (uint32_t)__cvta_generic_to_shared(gsm);

    const int z = blockIdx.z;
    const __half* W = of ? W0 : W0 + (size_t)z * WN;
    const float* bias = (z == 0) ? b0 : (z == 1) ? b1 : b2;
    __half* oh = (z == 0) ? o0 : (z == 1) ? o1 : o2;

    const int tid  = threadIdx.x;
    const int lane = tid & 31;
    const int w    = tid >> 5;
    const int g    = lane >> 2;
    const int tg   = lane & 3;
    const int wr   = w >> 1;
    const int wc   = w & 1;

    const int m0 = blockIdx.y * 128;
    const int n0 = blockIdx.x * 128;
    const int arow = wr * 32;
    const int brow = wc * 64;

    const int lr16 = lane & 15;
    const int hi16 = lane >> 4;
    const uint32_t a_base = (uint32_t)((arow + lr16) * 144 + hi16 * 16);
    const uint32_t b_base = (uint32_t)((brow + (hi16 << 3) + (lane & 7)) * 144
                                       + ((lane >> 3) & 1) * 16);

    // loader: A/B each 128 rows x 8 chunks(16B) = 1024 chunks, 4 per thread
    auto loadStage = [&](int s, int k0) {
        const uint32_t sb = sbase + s * G_STAGE_B;
#pragma unroll
        for (int i = 0; i < 4; i++) {
            int id = tid + i * 256;
            int row = id >> 3, c = id & 7;
            CP_ASYNC16(sb + (uint32_t)(row * G_STR + c * 8) * 2,
                       A + (size_t)(m0 + row) * K + k0 + c * 8);
            CP_ASYNC16(sb + G_TILE_B + (uint32_t)(row * G_STR + c * 8) * 2,
                       W + (size_t)(n0 + row) * K + k0 + c * 8);
        }
    };

    float acc[2][8][4];
#pragma unroll
    for (int mi = 0; mi < 2; mi++)
#pragma unroll
        for (int nt = 0; nt < 8; nt++)
#pragma unroll
            for (int j = 0; j < 4; j++) acc[mi][nt][j] = 0.f;

    loadStage(0, 0);   CP_COMMIT();
    loadStage(1, 64);  CP_COMMIT();

    const int nIter = K / 64;   // 12
    for (int t = 0; t < nIter; ++t) {
        if (t + 1 < nIter) { CP_WAIT1(); } else { CP_WAIT0(); }
        __syncthreads();

        const uint32_t sA = sbase + (t % 3) * G_STAGE_B;
        const uint32_t sB = sA + G_TILE_B;
#pragma unroll
        for (int k16 = 0; k16 < 4; k16++) {
            uint32_t a0[4], a1[4];
            LDSM_X4(a0, sA + a_base + k16 * 32);
            LDSM_X4(a1, sA + a_base + 16 * 144 + k16 * 32);
#pragma unroll
            for (int p = 0; p < 4; p++) {
                uint32_t bb[4];
                LDSM_X4(bb, sB + b_base + p * 16 * 144 + k16 * 32);
                MMA16F(acc[0][p * 2],     a0, bb[0], bb[1]);
                MMA16F(acc[0][p * 2 + 1], a0, bb[2], bb[3]);
                MMA16F(acc[1][p * 2],     a1, bb[0], bb[1]);
                MMA16F(acc[1][p * 2 + 1], a1, bb[2], bb[3]);
            }
        }

        if (t + 2 < nIter) {
            loadStage((t + 2) % 3, (t + 2) * 64);
            CP_COMMIT();
        }
    }

    // epilogue
#pragma unroll
    for (int nt = 0; nt < 8; nt++) {
        int c0 = n0 + brow + nt * 8 + tg * 2;
        float2 bb = *(const float2*)&bias[c0];
#pragma unroll
        for (int mi = 0; mi < 2; mi++) {
            int r0 = m0 + arow + mi * 16 + g;
            float x0 = acc[mi][nt][0] + bb.x, y0 = acc[mi][nt][1] + bb.y;
            float x1 = acc[mi][nt][2] + bb.x, y1 = acc[mi][nt][3] + bb.y;
            if (of) {
                *(float2*)&of[(size_t)r0 * N + c0]       = make_float2(x0, y0);
                *(float2*)&of[(size_t)(r0 + 8) * N + c0] = make_float2(x1, y1);
            } else {
                *(__half2*)&oh[(size_t)r0 * N + c0]       = __floats2half2_rn(x0, y0);
                *(__half2*)&oh[(size_t)(r0 + 8) * N + c0] = __floats2half2_rn(x1, y1);
            }
        }
    }
}

// ---------------------------------------------------------------------------
// fp16 flash attention: m16n8k16 mma, ldmatrix(.trans) fragments, cp.async
// double buffer. Br=64 q rows, Bc=32 keys/stage, 256 threads (8 warps 4x2).
// smem 111360B -> 2 CTA/SM. Ps(f32 scores) aliases Pb(fp16 P) with a barrier.
// ---------------------------------------------------------------------------
#define AQ_STR  264   // halfs per Q/K/V row
#define APB_STR 40    // halfs per P row
#define APS_STR 36    // floats per S row
#define A_KS_H (64 * AQ_STR)
#define A_VS_H (A_KS_H + 2 * 32 * AQ_STR)
#define A_UNION_B ((A_VS_H + 2 * 32 * AQ_STR) * 2)   // 101376
#define A_ST_B (A_UNION_B + 64 * APS_STR * 4)        // +9216
#define ATTN_SMEM_BYTES (A_ST_B + 768)               // 111360

__global__ __launch_bounds__(256, 2) void attn_fp16_kernel(
    const __half* __restrict__ Q, const __half* __restrict__ K,
    const __half* __restrict__ V, __half* __restrict__ O)
{
    extern __shared__ char attsm[];
    const uint32_t sbase = (uint32_t)__cvta_generic_to_shared(attsm);
    float* Ps   = (float*)(attsm + A_UNION_B);
    float* sm_m = (float*)(attsm + A_ST_B);
    float* sm_l = sm_m + 64;
    float* sm_a = sm_l + 64;

    const int tid  = threadIdx.x;
    const int lane = tid & 31;
    const int w    = tid >> 5;
    const int g    = lane >> 2;
    const int tg   = lane & 3;
    const int wr   = w >> 1;
    const int wc   = w & 1;

    const int bh = blockIdx.y;
    const int b  = bh / H_DIM;
    const int h  = bh % H_DIM;
    const int t0 = blockIdx.x * 64;
    const size_t head = (size_t)b * F_DIM + (size_t)h * DH;

    // prologue: Q tile (64x32 chunks) + K/V stage 0 (32x32 each)
    {
#pragma unroll
        for (int i = 0; i < 8; i++) {
            int id = tid + i * 256;
            int row = id >> 5, c = id & 31;
            CP_ASYNC16(sbase + (uint32_t)(row * AQ_STR + c * 8) * 2,
                       Q + (size_t)(t0 + row) * ROW_STRIDE + head + c * 8);
        }
#pragma unroll
        for (int i = 0; i < 4; i++) {
            int id = tid + i * 256;
            int row = id >> 5, c = id & 31;
            size_t ga = (size_t)row * ROW_STRIDE + head + c * 8;
            CP_ASYNC16(sbase + (uint32_t)((A_KS_H + row * AQ_STR + c * 8)) * 2, K + ga);
            CP_ASYNC16(sbase + (uint32_t)((A_VS_H + row * AQ_STR + c * 8)) * 2, V + ga);
        }
        CP_COMMIT();
    }

    if (tid < 64) { sm_m[tid] = -1e30f; sm_l[tid] = 0.f; }

    float oacc[16][4];
#pragma unroll
    for (int nt = 0; nt < 16; nt++)
#pragma unroll
        for (int j = 0; j < 4; j++) oacc[nt][j] = 0.f;

    const int rq = wr * 16, ck = wc * 16;
    const int ro = wr * 16, co = wc * 128;

    const int lr16 = lane & 15;
    const int hi16 = lane >> 4;
    const uint32_t qoff = sbase + (uint32_t)((rq + lr16) * AQ_STR) * 2 + hi16 * 16;
    const uint32_t koff = (uint32_t)((ck + (hi16 << 3) + (lane & 7)) * AQ_STR) * 2
                          + ((lane >> 3) & 1) * 16;
    const uint32_t poff = sbase + A_UNION_B
                          + (uint32_t)((ro + lr16) * APB_STR) * 2 + hi16 * 16;

    const int sr = tid >> 2, qd = tid & 3;

    for (int t = 0; t < 64; ++t) {
        const int cur = t & 1;
        CP_WAIT0();
        __syncthreads();

        // prefetch next K/V stage
        if (t + 1 < 64) {
            const int nxt = cur ^ 1;
            const int s0 = (t + 1) * 32;
#pragma unroll
            for (int i = 0; i < 4; i++) {
                int id = tid + i * 256;
                int row = id >> 5, c = id & 31;
                size_t ga = (size_t)(s0 + row) * ROW_STRIDE + head + c * 8;
                CP_ASYNC16(sbase + (uint32_t)((A_KS_H + (nxt * 32 + row) * AQ_STR + c * 8)) * 2, K + ga);
                CP_ASYNC16(sbase + (uint32_t)((A_VS_H + (nxt * 32 + row) * AQ_STR + c * 8)) * 2, V + ga);
            }
            CP_COMMIT();
        }

        // ---- S = Q K^T : warp tile 16x16 (2 n8-blocks) ----
        float sacc[2][4];
#pragma unroll
        for (int nt = 0; nt < 2; nt++)
#pragma unroll
            for (int j = 0; j < 4; j++) sacc[nt][j] = 0.f;

        const uint32_t kb = sbase + (uint32_t)(A_KS_H + cur * 32 * AQ_STR) * 2 + koff;
#pragma unroll
        for (int k16 = 0; k16 < 16; k16++) {
            uint32_t a[4], bb[4];
            LDSM_X4(a,  qoff + k16 * 32);
            LDSM_X4(bb, kb   + k16 * 32);
            MMA16F(sacc[0], a, bb[0], bb[1]);
            MMA16F(sacc[1], a, bb[2], bb[3]);
        }

        // store S (f32)
#pragma unroll
        for (int nt = 0; nt < 2; nt++) {
            int c0 = ck + nt * 8 + tg * 2;
            *(float2*)&Ps[(rq + g)     * APS_STR + c0] = make_float2(sacc[nt][0], sacc[nt][1]);
            *(float2*)&Ps[(rq + g + 8) * APS_STR + c0] = make_float2(sacc[nt][2], sacc[nt][3]);
        }
        __syncthreads();

        // ---- online softmax (regs) ----
        float4 v0 = *(float4*)&Ps[sr * APS_STR + qd * 8];
        float4 v1 = *(float4*)&Ps[sr * APS_STR + qd * 8 + 4];
        {
            const float sc = 0.125f;
            v0.x *= sc; v0.y *= sc; v0.z *= sc; v0.w *= sc;
            v1.x *= sc; v1.y *= sc; v1.z *= sc; v1.w *= sc;
        }
        float mx = fmaxf(fmaxf(fmaxf(v0.x, v0.y), fmaxf(v0.z, v0.w)),
                         fmaxf(fmaxf(v1.x, v1.y), fmaxf(v1.z, v1.w)));
        mx = fmaxf(mx, __shfl_xor_sync(0xffffffffu, mx, 1));
        mx = fmaxf(mx, __shfl_xor_sync(0xffffffffu, mx, 2));

        float m_old = sm_m[sr];
        float m_new = fmaxf(m_old, mx);
        float alpha = __expf(m_old - m_new);

        v0.x = __expf(v0.x - m_new); v0.y = __expf(v0.y - m_new);
        v0.z = __expf(v0.z - m_new); v0.w = __expf(v0.w - m_new);
        v1.x = __expf(v1.x - m_new); v1.y = __expf(v1.y - m_new);
        v1.z = __expf(v1.z - m_new); v1.w = __expf(v1.w - m_new);

        float s = (v0.x + v0.y + v0.z + v0.w) + (v1.x + v1.y + v1.z + v1.w);
        s += __shfl_xor_sync(0xffffffffu, s, 1);
        s += __shfl_xor_sync(0xffffffffu, s, 2);

        __syncthreads();   // all S reads complete before Pb overwrite

        // write P (fp16) into union region + stats
        {
            __half2 p0 = __floats2half2_rn(v0.x, v0.y);
            __half2 p1 = __floats2half2_rn(v0.z, v0.w);
            __half2 p2 = __floats2half2_rn(v1.x, v1.y);
            __half2 p3 = __floats2half2_rn(v1.z, v1.w);
            uint4 u;
            u.x = *(uint32_t*)&p0; u.y = *(uint32_t*)&p1;
            u.z = *(uint32_t*)&p2; u.w = *(uint32_t*)&p3;
            *(uint4*)(attsm + A_UNION_B + sr * (APB_STR * 2) + qd * 16) = u;
        }
        if (qd == 0) {
            sm_m[sr] = m_new;
            sm_l[sr] = sm_l[sr] * alpha + s;
            sm_a[sr] = alpha;
        }
        __syncthreads();

        // ---- rescale O, then O += P V : warp tile 16x128 ----
        {
            float al0 = sm_a[ro + g];
            float al1 = sm_a[ro + g + 8];
#pragma unroll
            for (int nt = 0; nt < 16; nt++) {
                oacc[nt][0] *= al0; oacc[nt][1] *= al0;
                oacc[nt][2] *= al1; oacc[nt][3] *= al1;
            }
        }
        const uint32_t vb = sbase + (uint32_t)(A_VS_H + cur * 32 * AQ_STR) * 2;
#pragma unroll
        for (int kst = 0; kst < 2; kst++) {
            uint32_t a[4];
            LDSM_X4(a, poff + kst * 32);
            const uint32_t vrow = vb + (uint32_t)((kst * 16 + lr16) * AQ_STR) * 2
                                  + hi16 * 16;
#pragma unroll
            for (int ntp = 0; ntp < 8; ntp++) {
                uint32_t bv[4];
                LDSM_X4T(bv, vrow + (uint32_t)(co + ntp * 16) * 2);
                MMA16F(oacc[ntp * 2],     a, bv[0], bv[1]);
                MMA16F(oacc[ntp * 2 + 1], a, bv[2], bv[3]);
            }
        }
    }

    // ---- epilogue: normalize, write fp16 O ----
    {
        float il0 = 1.f / sm_l[ro + g];
        float il1 = 1.f / sm_l[ro + g + 8];
        size_t r0 = (size_t)(t0 + ro + g)     * ROW_STRIDE + head + co;
        size_t r1 = (size_t)(t0 + ro + g + 8) * ROW_STRIDE + head + co;
#pragma unroll
        for (int nt = 0; nt < 16; nt++) {
            int c0 = nt * 8 + tg * 2;
            *(__half2*)&O[r0 + c0] =
                __floats2half2_rn(oacc[nt][0] * il0, oacc[nt][1] * il0);
            *(__half2*)&O[r1 + c0] =
                __floats2half2_rn(oacc[nt][2] * il1, oacc[nt][3] * il1);
        }
    }
}

// ---------------------------------------------------------------------------
extern "C" void kernel_launch(void* const* d_in, const int* in_sizes, int n_in,
                              void* d_out, int out_size)
{
    const float* x  = (const float*)d_in[0];
    const float* Wq = (const float*)d_in[1];
    const float* bq = (const float*)d_in[2];
    const float* Wk = (const float*)d_in[3];
    const float* bk = (const float*)d_in[4];
    const float* Wv = (const float*)d_in[5];
    const float* bv = (const float*)d_in[6];
    const float* Wo = (const float*)d_in[7];
    const float* bo = (const float*)d_in[8];
    float* out = (float*)d_out;

    __half *x16, *Q16, *K16, *V16, *O16, *W16;
    cudaGetSymbolAddress((void**)&x16, g_x16);
    cudaGetSymbolAddress((void**)&Q16, g_Q16);
    cudaGetSymbolAddress((void**)&K16, g_K16);
    cudaGetSymbolAddress((void**)&V16, g_V16);
    cudaGetSymbolAddress((void**)&O16, g_O16);
    cudaGetSymbolAddress((void**)&W16, g_W16);

    // converts
    conv_half_kernel<<<XN / 2048, 256>>>(x, x16, XN);
    conv_w4_kernel<<<dim3(WN / 2048, 4), 256>>>(Wq, Wk, Wv, Wo, W16);

    cudaFuncSetAttribute(gemm_fp16_kernel,
                         cudaFuncAttributeMaxDynamicSharedMemorySize,
                         GEMM_SMEM_BYTES);
    cudaFuncSetAttribute(attn_fp16_kernel,
                         cudaFuncAttributeMaxDynamicSharedMemorySize,
                         ATTN_SMEM_BYTES);

    // fused Q/K/V projections (grid.z selects weight/bias/output)
    gemm_fp16_kernel<<<dim3(F_DIM / 128, M_ROWS / 128, 3), 256, GEMM_SMEM_BYTES>>>(
        x16, W16, bq, bk, bv, Q16, K16, V16, nullptr, M_ROWS, F_DIM, F_DIM);

    // attention
    attn_fp16_kernel<<<dim3(T_DIM / 64, B_DIM * H_DIM), 256, ATTN_SMEM_BYTES>>>(
        Q16, K16, V16, O16);

    // output projection (f32 out)
    gemm_fp16_kernel<<<dim3(F_DIM / 128, M_ROWS / 128, 1), 256, GEMM_SMEM_BYTES>>>(
        O16, W16 + (size_t)3 * WN, bo, bo, bo, nullptr, nullptr, nullptr,
        out, M_ROWS, F_DIM, F_DIM);
}